// round 11
// baseline (speedup 1.0000x reference)
#include <cuda_runtime.h>
#include <math.h>

#define BB   16
#define NN   4096
#define EE   65536
#define HH   512
#define MM1  1024
#define MM2  32768

#define NBLK 444          // 3*148; launch_bounds(256,4) guarantees capacity 592
#define NTHR 256

// ---- device scratch. NEVER named in host code (host shadows + ATS would
// silently write host memory and trip the harness mem guard). ---------------
__device__ int   g_deg[NN];
__device__ int   g_off[NN + 1];
__device__ int   g_cur[NN];
__device__ int   g_src[EE];
__device__ float g_hA [(size_t)BB * NN * 32];
__device__ float g_hB [(size_t)BB * NN * 32];
__device__ float g_as0[(size_t)BB * NN], g_ad0[(size_t)BB * NN];
__device__ float g_as1[(size_t)BB * NN], g_ad1[(size_t)BB * NN];
__device__ float g_gi [(size_t)BB * 3 * HH];
__device__ float g_gh [(size_t)BB * 3 * HH];
__device__ float g_nh [(size_t)BB * HH];
__device__ float g_o1 [(size_t)BB * MM1];
__device__ unsigned int g_bar_count;
__device__ unsigned int g_bar_gen;

// ---- software grid barrier (sense-reversing; survives graph replays) ------
__device__ __forceinline__ void grid_bar() {
    __syncthreads();
    if (threadIdx.x == 0) {
        __threadfence();
        unsigned my = atomicAdd(&g_bar_gen, 0u);      // read BEFORE arriving
        unsigned arr = atomicAdd(&g_bar_count, 1u);
        if (arr == gridDim.x - 1) {
            atomicExch(&g_bar_count, 0u);
            __threadfence();
            atomicAdd(&g_bar_gen, 1u);
        } else {
            while (atomicAdd(&g_bar_gen, 0u) == my) __nanosleep(64);
        }
        __threadfence();
    }
    __syncthreads();
}

__device__ __forceinline__ float lrelu(float v) { return v >= 0.f ? v : 0.2f * v; }

// ---- warp rowgemm: C[b][row] = A[b]·W[row] + bias, 16 batches -------------
__device__ __forceinline__ void rowgemm_warp(
    const float* __restrict__ A, const float* __restrict__ W,
    const float* __restrict__ bias,
    const float* pr, const float* bg, const float* bb, bool epi,
    float* __restrict__ C, int row, int M, int K, int lane) {
    float acc[16];
#pragma unroll
    for (int b2 = 0; b2 < 16; b2++) acc[b2] = 0.f;
    const float* w = W + (size_t)row * K;
    for (int k = lane * 4; k < K; k += 128) {
        float4 wv = *(const float4*)(w + k);
#pragma unroll
        for (int b2 = 0; b2 < 16; b2++) {
            float4 av = *(const float4*)(A + (size_t)b2 * K + k);
            acc[b2] += wv.x * av.x + wv.y * av.y + wv.z * av.z + wv.w * av.w;
        }
    }
#pragma unroll
    for (int b2 = 0; b2 < 16; b2++) {
#pragma unroll
        for (int o = 16; o > 0; o >>= 1) acc[b2] += __shfl_xor_sync(0xffffffffu, acc[b2], o);
    }
    if (lane == 0) {
        const float inv = rsqrtf(1.f + 1e-5f);
#pragma unroll
        for (int b2 = 0; b2 < 16; b2++) {
            float t = acc[b2] + bias[row];
            if (epi) {
                t = t >= 0.f ? t : pr[row] * t;
                t = t * inv * bg[row] + bb[row];
            }
            C[(size_t)b2 * M + row] = t;
        }
    }
}

// ---- single-pass GAT aggregate (no max subtraction; values bounded) -------
// LAYER 0: hA/as0/ad0;  LAYER 1: hB/as1/ad1. Returns per-lane feature.
template <int LAYER>
__device__ __forceinline__ float gat_aggregate(int gw, int lane, int b, int d) {
    const float* asv = (LAYER == 0) ? g_as0 : g_as1;
    const float* adv = (LAYER == 0) ? g_ad0 : g_ad1;
    const float* hsrc = (LAYER == 0) ? g_hA : g_hB;
    const float* asb = asv + (size_t)b * NN;
    const float* hb = hsrc + (size_t)b * NN * 32;
    float add = adv[gw];
    int beg = g_off[d], end = g_off[d + 1];

    float wself = expf(lrelu(asb[d] + add));
    float wpart = (lane == 0) ? wself : 0.f;
    float acc = wself * hb[(size_t)d * 32 + lane];
    for (int base = beg; base < end; base += 32) {
        int cnt = end - base; if (cnt > 32) cnt = 32;
        int s = (lane < cnt) ? g_src[base + lane] : 0;
        float w = (lane < cnt) ? expf(lrelu(asb[s] + add)) : 0.f;
        wpart += w;
        for (int k = 0; k < cnt; k++) {
            float wk = __shfl_sync(0xffffffffu, w, k);
            int   sk = __shfl_sync(0xffffffffu, s, k);
            acc += wk * hb[(size_t)sk * 32 + lane];
        }
    }
#pragma unroll
    for (int o = 16; o > 0; o >>= 1) wpart += __shfl_xor_sync(0xffffffffu, wpart, o);
    return acc / wpart;
}

// ---------------- the mega kernel ------------------------------------------
__global__ void __launch_bounds__(NTHR, 4) k_mega(
    const float* __restrict__ x, const float* __restrict__ svp,
    const float* __restrict__ hidden, const int* __restrict__ ei,
    const float* __restrict__ W0, const float* __restrict__ a0s,
    const float* __restrict__ a0d, const float* __restrict__ b0,
    const float* __restrict__ W1, const float* __restrict__ a1s,
    const float* __restrict__ a1d, const float* __restrict__ b1,
    const float* __restrict__ w_ih, const float* __restrict__ w_hh,
    const float* __restrict__ b_ih, const float* __restrict__ b_hh,
    const float* __restrict__ l1w, const float* __restrict__ l1b,
    const float* __restrict__ pr1, const float* __restrict__ bg1,
    const float* __restrict__ bb1, const float* __restrict__ l2w,
    const float* __restrict__ l2b, const float* __restrict__ pr2,
    const float* __restrict__ bg2, const float* __restrict__ bb2,
    const float* __restrict__ wo, const float* __restrict__ bo,
    float* __restrict__ out, int write_nh) {
    int tid = threadIdx.x;
    int gtid = blockIdx.x * NTHR + tid;
    int gstride = gridDim.x * NTHR;
    int lane = tid & 31;
    int gwarp = gtid >> 5;
    int gwarps = gstride >> 5;

    // P0: zero degree histogram
    for (int i = gtid; i < NN; i += gstride) g_deg[i] = 0;
    grid_bar();

    // P1: histogram of dst
    for (int i = gtid; i < EE; i += gstride) atomicAdd(&g_deg[ei[EE + i]], 1);
    grid_bar();

    // P2: exclusive scan (block 0 only)
    if (blockIdx.x == 0) {
        __shared__ int s_scan[NTHR];
        int base = tid * 16;
        int v[16]; int sum = 0;
#pragma unroll
        for (int i = 0; i < 16; i++) { v[i] = g_deg[base + i]; sum += v[i]; }
        s_scan[tid] = sum;
        __syncthreads();
        for (int o = 1; o < NTHR; o <<= 1) {
            int t2 = (tid >= o) ? s_scan[tid - o] : 0;
            __syncthreads();
            s_scan[tid] += t2;
            __syncthreads();
        }
        int run = s_scan[tid] - sum;
#pragma unroll
        for (int i = 0; i < 16; i++) {
            g_off[base + i] = run; g_cur[base + i] = run; run += v[i];
        }
        if (tid == NTHR - 1) g_off[NN] = run;
    }
    grid_bar();

    // P3: scatter src by dst
    for (int i = gtid; i < EE; i += gstride) {
        int d = ei[EE + i];
        int pos = atomicAdd(&g_cur[d], 1);
        g_src[pos] = ei[i];
    }
    grid_bar();

    // P4: GRU gemms (3072 row units) + feat3 (65536 warp units)
    {
        const int U_GI = 3 * HH, U_GH = 3 * HH;
        int total = U_GI + U_GH + BB * NN;
        for (int u = gwarp; u < total; u += gwarps) {
            if (u < U_GI) {
                rowgemm_warp(x, w_ih, b_ih, 0, 0, 0, false, g_gi, u, 3 * HH, 256, lane);
            } else if (u < U_GI + U_GH) {
                rowgemm_warp(hidden, w_hh, b_hh, 0, 0, 0, false, g_gh, u - U_GI, 3 * HH, HH, lane);
            } else {
                int gw = u - U_GI - U_GH;
                const float* xv = svp + (size_t)gw * 3;
                float v0 = xv[0], v1 = xv[1], v2 = xv[2];
                float hv = W0[lane * 3] * v0 + W0[lane * 3 + 1] * v1 + W0[lane * 3 + 2] * v2;
                g_hA[(size_t)gw * 32 + lane] = hv;
                float ps = hv * a0s[lane];
                float pd = hv * a0d[lane];
#pragma unroll
                for (int o = 16; o > 0; o >>= 1) {
                    ps += __shfl_xor_sync(0xffffffffu, ps, o);
                    pd += __shfl_xor_sync(0xffffffffu, pd, o);
                }
                if (lane == 0) { g_as0[gw] = ps; g_ad0[gw] = pd; }
            }
        }
    }
    grid_bar();

    // P5: GRU combine (thread units) + agg0 fused with layer-1 transform
    for (int t = gtid; t < BB * HH; t += gstride) {
        int b = t / HH, j = t % HH;
        size_t base = (size_t)b * 3 * HH;
        float ir = g_gi[base + j], iz = g_gi[base + HH + j], in_ = g_gi[base + 2 * HH + j];
        float hr = g_gh[base + j], hz = g_gh[base + HH + j], hn = g_gh[base + 2 * HH + j];
        float r = 1.f / (1.f + expf(-(ir + hr)));
        float z = 1.f / (1.f + expf(-(iz + hz)));
        float n = tanhf(in_ + r * hn);
        float hp = hidden[(size_t)b * HH + j];
        float nh = (1.f - z) * n + z * hp;
        g_nh[(size_t)b * HH + j] = nh;
        if (write_nh) out[(size_t)BB * NN * 3 + (size_t)b * HH + j] = nh;
    }
    for (int gw = gwarp; gw < BB * NN; gw += gwarps) {
        int b = gw >> 12;
        int d = gw & (NN - 1);
        float gat = gat_aggregate<0>(gw, lane, b, d) + b0[lane];
        float hv = 0.f;
#pragma unroll
        for (int k = 0; k < 32; k++) {
            float gk = __shfl_sync(0xffffffffu, gat, k);
            hv += W1[lane * 32 + k] * gk;
        }
        g_hB[(size_t)gw * 32 + lane] = hv;
        float ps = hv * a1s[lane];
        float pd = hv * a1d[lane];
#pragma unroll
        for (int o = 16; o > 0; o >>= 1) {
            ps += __shfl_xor_sync(0xffffffffu, ps, o);
            pd += __shfl_xor_sync(0xffffffffu, pd, o);
        }
        if (lane == 0) { g_as1[gw] = ps; g_ad1[gw] = pd; }
    }
    grid_bar();

    // P6: lin1 (1024 row units) + agg1 fused with out projection (store)
    {
        int total = MM1 + BB * NN;
        for (int u = gwarp; u < total; u += gwarps) {
            if (u < MM1) {
                rowgemm_warp(g_nh, l1w, l1b, pr1, bg1, bb1, true, g_o1, u, MM1, HH, lane);
            } else {
                int gw = u - MM1;
                int b = gw >> 12;
                int d = gw & (NN - 1);
                float gat = gat_aggregate<1>(gw, lane, b, d) + b1[lane];
                float s0 = gat * wo[8 + lane];
                float s1 = gat * wo[48 + lane];
                float s2 = gat * wo[88 + lane];
#pragma unroll
                for (int o = 16; o > 0; o >>= 1) {
                    s0 += __shfl_xor_sync(0xffffffffu, s0, o);
                    s1 += __shfl_xor_sync(0xffffffffu, s1, o);
                    s2 += __shfl_xor_sync(0xffffffffu, s2, o);
                }
                if (lane == 0) {
                    size_t base = (size_t)gw * 3;
                    out[base + 0] = bo[0] + s0;
                    out[base + 1] = bo[1] + s1;
                    out[base + 2] = bo[2] + s2;
                }
            }
        }
    }
    grid_bar();

    // P7: lin2 (16384 2-row units) with scatter-add epilogue into out
    for (int u = gwarp; u < MM2 / 2; u += gwarps) {
        int m0 = u * 2;
        float acc0[16], acc1[16];
#pragma unroll
        for (int b2 = 0; b2 < 16; b2++) { acc0[b2] = 0.f; acc1[b2] = 0.f; }
        const float* w0 = l2w + (size_t)m0 * MM1;
        for (int k = lane * 4; k < MM1; k += 128) {
            float4 wv0 = __ldcs((const float4*)(w0 + k));
            float4 wv1 = __ldcs((const float4*)(w0 + MM1 + k));
#pragma unroll
            for (int b2 = 0; b2 < 16; b2++) {
                float4 av = *(const float4*)(g_o1 + (size_t)b2 * MM1 + k);
                acc0[b2] += wv0.x * av.x + wv0.y * av.y + wv0.z * av.z + wv0.w * av.w;
                acc1[b2] += wv1.x * av.x + wv1.y * av.y + wv1.z * av.z + wv1.w * av.w;
            }
        }
        float m0v = 0.f, m1v = 0.f;
#pragma unroll
        for (int b2 = 0; b2 < 16; b2++) {
            float v0 = acc0[b2], v1 = acc1[b2];
#pragma unroll
            for (int o = 16; o > 0; o >>= 1) {
                v0 += __shfl_xor_sync(0xffffffffu, v0, o);
                v1 += __shfl_xor_sync(0xffffffffu, v1, o);
            }
            if (lane == b2) { m0v = v0; m1v = v1; }
        }
        if (lane < 16) {
            const float inv = rsqrtf(1.f + 1e-5f);
            size_t ob = (size_t)lane * NN;
            float t0 = m0v + l2b[m0];
            t0 = t0 >= 0.f ? t0 : pr2[m0] * t0;
            t0 = t0 * inv * bg2[m0] + bb2[m0];
            int n0 = m0 >> 3, j0 = m0 & 7;
            atomicAdd(&out[(ob + n0) * 3 + 0], wo[j0] * t0);
            atomicAdd(&out[(ob + n0) * 3 + 1], wo[40 + j0] * t0);
            atomicAdd(&out[(ob + n0) * 3 + 2], wo[80 + j0] * t0);
            int m1 = m0 + 1;
            float t1 = m1v + l2b[m1];
            t1 = t1 >= 0.f ? t1 : pr2[m1] * t1;
            t1 = t1 * inv * bg2[m1] + bb2[m1];
            int n1 = m1 >> 3, j1 = m1 & 7;
            atomicAdd(&out[(ob + n1) * 3 + 0], wo[j1] * t1);
            atomicAdd(&out[(ob + n1) * 3 + 1], wo[40 + j1] * t1);
            atomicAdd(&out[(ob + n1) * 3 + 2], wo[80 + j1] * t1);
        }
    }
}

// ---------------- launch ----------------------------------------------------
extern "C" void kernel_launch(void* const* d_in, const int* in_sizes, int n_in,
                              void* d_out, int out_size) {
    const float* x      = (const float*)d_in[0];
    const float* svp    = (const float*)d_in[1];
    const float* hidden = (const float*)d_in[2];
    const int*   ei     = (const int*)  d_in[3];
    const float* W0     = (const float*)d_in[4];
    const float* a0s    = (const float*)d_in[5];
    const float* a0d    = (const float*)d_in[6];
    const float* b0     = (const float*)d_in[7];
    const float* W1     = (const float*)d_in[8];
    const float* a1s    = (const float*)d_in[9];
    const float* a1d    = (const float*)d_in[10];
    const float* b1     = (const float*)d_in[11];
    const float* w_ih   = (const float*)d_in[12];
    const float* w_hh   = (const float*)d_in[13];
    const float* b_ih   = (const float*)d_in[14];
    const float* b_hh   = (const float*)d_in[15];
    const float* l1w    = (const float*)d_in[16];
    const float* l1b    = (const float*)d_in[17];
    const float* pr1    = (const float*)d_in[18];
    const float* bg1    = (const float*)d_in[19];
    const float* bb1    = (const float*)d_in[20];
    const float* l2w    = (const float*)d_in[21];
    const float* l2b    = (const float*)d_in[22];
    const float* pr2    = (const float*)d_in[23];
    const float* bg2    = (const float*)d_in[24];
    const float* bb2    = (const float*)d_in[25];
    const float* wo     = (const float*)d_in[26];
    const float* bo     = (const float*)d_in[27];
    float* out = (float*)d_out;

    int write_nh = (out_size >= BB * NN * 3 + BB * HH) ? 1 : 0;

    k_mega<<<NBLK, NTHR>>>(x, svp, hidden, ei,
                           W0, a0s, a0d, b0, W1, a1s, a1d, b1,
                           w_ih, w_hh, b_ih, b_hh,
                           l1w, l1b, pr1, bg1, bb1,
                           l2w, l2b, pr2, bg2, bb2,
                           wo, bo, out, write_nh);
}

// round 13
// speedup vs baseline: 1.2340x; 1.2340x over previous
#include <cuda_runtime.h>
#include <math.h>

#define BB   16
#define NN   4096
#define EE   65536
#define HH   512
#define MM1  1024
#define MM2  32768

// ---- device scratch. NEVER named in host code (host shadows + ATS would
// silently write host memory and trip the harness mem guard). ---------------
__device__ int   g_deg[NN];
__device__ int   g_off[NN + 1];
__device__ int   g_cur[NN];
__device__ int   g_src[EE];
__device__ float g_hA [(size_t)BB * NN * 32];
__device__ float g_hB [(size_t)BB * NN * 32];
__device__ float g_w  [(size_t)BB * EE];        // edge softmax weights
__device__ float g_as0[(size_t)BB * NN], g_ad0[(size_t)BB * NN];
__device__ float g_as1[(size_t)BB * NN], g_ad1[(size_t)BB * NN];
__device__ float g_gi [(size_t)BB * 3 * HH];
__device__ float g_gh [(size_t)BB * 3 * HH];
__device__ float g_nh [(size_t)BB * HH];
__device__ float g_o1 [(size_t)BB * MM1];

// ---------------- CSR build ------------------------------------------------
__global__ void k_zero_deg(int n) {
    int i = blockIdx.x * blockDim.x + threadIdx.x;
    if (i < n) g_deg[i] = 0;
}
__global__ void k_hist(const int* __restrict__ ei, int n) {
    int i = blockIdx.x * blockDim.x + threadIdx.x;
    if (i < n) atomicAdd(&g_deg[ei[EE + i]], 1);
}
__global__ void k_scan(int active) {
    if (!active) return;
    __shared__ int s[1024];
    int tid = threadIdx.x;
    int b4 = tid * 4;
    int v0 = g_deg[b4], v1 = g_deg[b4 + 1], v2 = g_deg[b4 + 2], v3 = g_deg[b4 + 3];
    int sum = v0 + v1 + v2 + v3;
    s[tid] = sum;
    __syncthreads();
    for (int o = 1; o < 1024; o <<= 1) {
        int t = (tid >= o) ? s[tid - o] : 0;
        __syncthreads();
        s[tid] += t;
        __syncthreads();
    }
    int excl = s[tid] - sum;
    int o0 = excl, o1 = excl + v0, o2 = o1 + v1, o3 = o2 + v2;
    g_off[b4] = o0; g_off[b4 + 1] = o1; g_off[b4 + 2] = o2; g_off[b4 + 3] = o3;
    g_cur[b4] = o0; g_cur[b4 + 1] = o1; g_cur[b4 + 2] = o2; g_cur[b4 + 3] = o3;
    if (tid == 1023) g_off[NN] = s[1023];
}
__global__ void k_scatter(const int* __restrict__ ei, int n) {
    int i = blockIdx.x * blockDim.x + threadIdx.x;
    if (i < n) {
        int d = ei[EE + i];
        int pos = atomicAdd(&g_cur[d], 1);
        g_src[pos] = ei[i];
    }
}

__device__ __forceinline__ float lrelu(float v) { return v >= 0.f ? v : 0.2f * v; }

// ---- layer-0 features: warp per (b,n), lane = feature ---------------------
__global__ void k_feat3(const float* __restrict__ svp,
                        const float* __restrict__ W0,
                        const float* __restrict__ a0s,
                        const float* __restrict__ a0d,
                        int nwork) {
    int gw = (blockIdx.x * blockDim.x + threadIdx.x) >> 5;
    int lane = threadIdx.x & 31;
    if (gw >= nwork) return;
    const float* xv = svp + (size_t)gw * 3;
    float v0 = xv[0], v1 = xv[1], v2 = xv[2];
    float hv = W0[lane * 3] * v0 + W0[lane * 3 + 1] * v1 + W0[lane * 3 + 2] * v2;
    g_hA[(size_t)gw * 32 + lane] = hv;
    float ps = hv * a0s[lane];
    float pd = hv * a0d[lane];
#pragma unroll
    for (int o = 16; o > 0; o >>= 1) {
        ps += __shfl_xor_sync(0xffffffffu, ps, o);
        pd += __shfl_xor_sync(0xffffffffu, pd, o);
    }
    if (lane == 0) { g_as0[gw] = ps; g_ad0[gw] = pd; }
}

// ---- single-pass GAT aggregate, NO inner-loop shfls -----------------------
// Pass A: lane-parallel edge weights -> g_w (coalesced). __syncwarp orders.
// Pass B: uniform-broadcast loads of w/src + coalesced h gather (4-cyc FMA
// chain only; iterations otherwise independent -> pipelineable).
template <int LAYER>
__device__ __forceinline__ float gat_aggregate(int gw, int lane, int b, int d) {
    const float* asv = (LAYER == 0) ? g_as0 : g_as1;
    const float* adv = (LAYER == 0) ? g_ad0 : g_ad1;
    const float* hsrc = (LAYER == 0) ? g_hA : g_hB;
    const float* asb = asv + (size_t)b * NN;
    const float* hb = hsrc + (size_t)b * NN * 32;
    float add = adv[gw];
    int beg = g_off[d], end = g_off[d + 1];
    float* wb = g_w + (size_t)b * EE;

    // pass A: weights, lane-parallel
    float wsum = 0.f;
    for (int i = beg + lane; i < end; i += 32) {
        float w = expf(lrelu(asb[g_src[i]] + add));
        wb[i] = w;
        wsum += w;
    }
#pragma unroll
    for (int o = 16; o > 0; o >>= 1) wsum += __shfl_xor_sync(0xffffffffu, wsum, o);
    float wself = expf(lrelu(asb[d] + add));
    wsum += wself;
    __syncwarp();

    // pass B: aggregate with uniform loads (no shfl)
    float acc = wself * hb[(size_t)d * 32 + lane];
#pragma unroll 4
    for (int j = beg; j < end; j++) {
        float w = wb[j];
        int   s = g_src[j];
        acc += w * hb[(size_t)s * 32 + lane];
    }
    return acc / wsum;
}

// ---- aggregate layer 0 fused with layer-1 feature transform ---------------
__global__ void k_agg0_feat1(const float* __restrict__ b0,
                             const float* __restrict__ W1,
                             const float* __restrict__ a1s,
                             const float* __restrict__ a1d,
                             int nwork) {
    int gw = (blockIdx.x * blockDim.x + threadIdx.x) >> 5;
    int lane = threadIdx.x & 31;
    if (gw >= nwork) return;
    int b = gw >> 12;
    int d = gw & (NN - 1);

    float gat = gat_aggregate<0>(gw, lane, b, d) + b0[lane];

    float hv = 0.f;
#pragma unroll
    for (int k = 0; k < 32; k++) {
        float gk = __shfl_sync(0xffffffffu, gat, k);
        hv += W1[lane * 32 + k] * gk;
    }
    g_hB[(size_t)gw * 32 + lane] = hv;
    float ps = hv * a1s[lane];
    float pd = hv * a1d[lane];
#pragma unroll
    for (int o = 16; o > 0; o >>= 1) {
        ps += __shfl_xor_sync(0xffffffffu, ps, o);
        pd += __shfl_xor_sync(0xffffffffu, pd, o);
    }
    if (lane == 0) { g_as1[gw] = ps; g_ad1[gw] = pd; }
}

// ---- aggregate layer 1 fused with output projection (stores out) ----------
__global__ void k_agg1_out(const float* __restrict__ b1,
                           const float* __restrict__ wo,   // [3 x 40]
                           const float* __restrict__ bo,   // [3]
                           float* __restrict__ out,
                           int nwork) {
    int gw = (blockIdx.x * blockDim.x + threadIdx.x) >> 5;
    int lane = threadIdx.x & 31;
    if (gw >= nwork) return;
    int b = gw >> 12;
    int d = gw & (NN - 1);

    float gat = gat_aggregate<1>(gw, lane, b, d) + b1[lane];

    float s0 = gat * wo[8 + lane];
    float s1 = gat * wo[48 + lane];
    float s2 = gat * wo[88 + lane];
#pragma unroll
    for (int o = 16; o > 0; o >>= 1) {
        s0 += __shfl_xor_sync(0xffffffffu, s0, o);
        s1 += __shfl_xor_sync(0xffffffffu, s1, o);
        s2 += __shfl_xor_sync(0xffffffffu, s2, o);
    }
    if (lane == 0) {
        size_t base = (size_t)gw * 3;
        out[base + 0] = bo[0] + s0;
        out[base + 1] = bo[1] + s1;
        out[base + 2] = bo[2] + s2;
    }
}

// ---------------- small GEMMs: scratch chosen by selectors ------------------
template <bool EPI>
__global__ void k_rowgemm(const float* __restrict__ Aext, int asel, int csel,
                          const float* __restrict__ W,
                          const float* __restrict__ bias,
                          const float* __restrict__ pr,
                          const float* __restrict__ bg,
                          const float* __restrict__ bb,
                          int M, int K) {
    const float* A = (asel == 1) ? (const float*)g_nh : Aext;
    float* C = (csel == 0) ? g_gi : (csel == 1) ? g_gh : g_o1;
    extern __shared__ float sA[];
    for (int i = threadIdx.x; i < 16 * K; i += blockDim.x) sA[i] = A[i];
    __syncthreads();
    int row = (blockIdx.x * blockDim.x + threadIdx.x) >> 5;
    int lane = threadIdx.x & 31;
    if (row >= M) return;
    const float* w = W + (size_t)row * K;
    float acc[16];
#pragma unroll
    for (int b2 = 0; b2 < 16; b2++) acc[b2] = 0.f;
    for (int k = lane * 4; k < K; k += 128) {
        float4 wv = *(const float4*)(w + k);
#pragma unroll
        for (int b2 = 0; b2 < 16; b2++) {
            float4 av = *(const float4*)(sA + b2 * K + k);
            acc[b2] += wv.x * av.x + wv.y * av.y + wv.z * av.z + wv.w * av.w;
        }
    }
#pragma unroll
    for (int b2 = 0; b2 < 16; b2++) {
#pragma unroll
        for (int o = 16; o > 0; o >>= 1) acc[b2] += __shfl_xor_sync(0xffffffffu, acc[b2], o);
    }
    if (lane == 0) {
        const float inv = rsqrtf(1.f + 1e-5f);
#pragma unroll
        for (int b2 = 0; b2 < 16; b2++) {
            float t = acc[b2] + bias[row];
            if (EPI) {
                t = t >= 0.f ? t : pr[row] * t;
                t = t * inv * bg[row] + bb[row];
            }
            C[(size_t)b2 * M + row] = t;
        }
    }
}

// ---- lin2 (32768x1024): 4 rows/warp, streaming weights, lane-parallel
// scatter-add epilogue. No launch_bounds: full register budget. -------------
__global__ void k_lin2_out(const float* __restrict__ W,
                           const float* __restrict__ bias,
                           const float* __restrict__ pr,
                           const float* __restrict__ bg,
                           const float* __restrict__ bb,
                           const float* __restrict__ wo,
                           float* __restrict__ out,
                           int nrows) {
    int warp = (blockIdx.x * blockDim.x + threadIdx.x) >> 5;
    int lane = threadIdx.x & 31;
    int m0 = warp * 4;
    if (m0 >= nrows) return;
    float acc[4][16];
#pragma unroll
    for (int r = 0; r < 4; r++)
#pragma unroll
        for (int b2 = 0; b2 < 16; b2++) acc[r][b2] = 0.f;

    const float* wr = W + (size_t)m0 * MM1;
    for (int k = lane * 4; k < MM1; k += 128) {
        float4 wv0 = __ldcs((const float4*)(wr + k));
        float4 wv1 = __ldcs((const float4*)(wr + MM1 + k));
        float4 wv2 = __ldcs((const float4*)(wr + 2 * MM1 + k));
        float4 wv3 = __ldcs((const float4*)(wr + 3 * MM1 + k));
#pragma unroll
        for (int b2 = 0; b2 < 16; b2++) {
            float4 av = *(const float4*)(g_o1 + (size_t)b2 * MM1 + k);
            acc[0][b2] += wv0.x * av.x + wv0.y * av.y + wv0.z * av.z + wv0.w * av.w;
            acc[1][b2] += wv1.x * av.x + wv1.y * av.y + wv1.z * av.z + wv1.w * av.w;
            acc[2][b2] += wv2.x * av.x + wv2.y * av.y + wv2.z * av.z + wv2.w * av.w;
            acc[3][b2] += wv3.x * av.x + wv3.y * av.y + wv3.z * av.z + wv3.w * av.w;
        }
    }
    float mine[4];
#pragma unroll
    for (int r = 0; r < 4; r++) {
        mine[r] = 0.f;
#pragma unroll
        for (int b2 = 0; b2 < 16; b2++) {
            float v = acc[r][b2];
#pragma unroll
            for (int o = 16; o > 0; o >>= 1) v += __shfl_xor_sync(0xffffffffu, v, o);
            if (lane == b2) mine[r] = v;
        }
    }
    if (lane < 16) {
        const float inv = rsqrtf(1.f + 1e-5f);
        size_t ob = (size_t)lane * NN;
#pragma unroll
        for (int r = 0; r < 4; r++) {
            int mrow = m0 + r;
            float t = mine[r] + bias[mrow];
            t = t >= 0.f ? t : pr[mrow] * t;
            t = t * inv * bg[mrow] + bb[mrow];
            int n = mrow >> 3, j = mrow & 7;
            atomicAdd(&out[(ob + n) * 3 + 0], wo[j] * t);
            atomicAdd(&out[(ob + n) * 3 + 1], wo[40 + j] * t);
            atomicAdd(&out[(ob + n) * 3 + 2], wo[80 + j] * t);
        }
    }
}

// ---------------- GRU combine ----------------------------------------------
__global__ void k_combine(const float* __restrict__ hidden, float* __restrict__ out,
                          int write_out, int nwork) {
    int t = blockIdx.x * blockDim.x + threadIdx.x;
    if (t >= nwork) return;
    int b = t / HH, j = t % HH;
    size_t base = (size_t)b * 3 * HH;
    float ir = g_gi[base + j], iz = g_gi[base + HH + j], in_ = g_gi[base + 2 * HH + j];
    float hr = g_gh[base + j], hz = g_gh[base + HH + j], hn = g_gh[base + 2 * HH + j];
    float r = 1.f / (1.f + expf(-(ir + hr)));
    float z = 1.f / (1.f + expf(-(iz + hz)));
    float n = tanhf(in_ + r * hn);
    float hp = hidden[(size_t)b * HH + j];
    float nh = (1.f - z) * n + z * hp;
    g_nh[(size_t)b * HH + j] = nh;
    if (write_out) out[(size_t)BB * NN * 3 + (size_t)b * HH + j] = nh;
}

// ---------------- launch ----------------------------------------------------
extern "C" void kernel_launch(void* const* d_in, const int* in_sizes, int n_in,
                              void* d_out, int out_size) {
    const float* x      = (const float*)d_in[0];
    const float* svp    = (const float*)d_in[1];
    const float* hidden = (const float*)d_in[2];
    const int*   ei     = (const int*)  d_in[3];
    const float* W0     = (const float*)d_in[4];
    const float* a0s    = (const float*)d_in[5];
    const float* a0d    = (const float*)d_in[6];
    const float* b0     = (const float*)d_in[7];
    const float* W1     = (const float*)d_in[8];
    const float* a1s    = (const float*)d_in[9];
    const float* a1d    = (const float*)d_in[10];
    const float* b1     = (const float*)d_in[11];
    const float* w_ih   = (const float*)d_in[12];
    const float* w_hh   = (const float*)d_in[13];
    const float* b_ih   = (const float*)d_in[14];
    const float* b_hh   = (const float*)d_in[15];
    const float* l1w    = (const float*)d_in[16];
    const float* l1b    = (const float*)d_in[17];
    const float* pr1    = (const float*)d_in[18];
    const float* bg1    = (const float*)d_in[19];
    const float* bb1    = (const float*)d_in[20];
    const float* l2w    = (const float*)d_in[21];
    const float* l2b    = (const float*)d_in[22];
    const float* pr2    = (const float*)d_in[23];
    const float* bg2    = (const float*)d_in[24];
    const float* bb2    = (const float*)d_in[25];
    const float* wo     = (const float*)d_in[26];
    const float* bo     = (const float*)d_in[27];
    float* out = (float*)d_out;

    int write_nh = (out_size >= BB * NN * 3 + BB * HH) ? 1 : 0;
    int warp_blks = (BB * NN) / 8;   // warp-per-(b,n) kernels, 8 warps/block

    // CSR build
    k_zero_deg<<<(NN + 255) / 256, 256>>>(NN);
    k_hist<<<(EE + 255) / 256, 256>>>(ei, EE);
    k_scan<<<1, 1024>>>(1);
    k_scatter<<<(EE + 255) / 256, 256>>>(ei, EE);

    // GAT (k_agg1_out STORES out = bo + GAT projection)
    k_feat3<<<warp_blks, 256>>>(svp, W0, a0s, a0d, BB * NN);
    k_agg0_feat1<<<warp_blks, 256>>>(b0, W1, a1s, a1d, BB * NN);
    k_agg1_out<<<warp_blks, 256>>>(b1, wo, bo, out, BB * NN);

    // GRU -> nh -> lin1 -> lin2 (atomic accumulate into out)
    k_rowgemm<false><<<(3 * HH + 7) / 8, 256, 16 * 256 * 4>>>(
        x, 0, 0, w_ih, b_ih, nullptr, nullptr, nullptr, 3 * HH, 256);
    k_rowgemm<false><<<(3 * HH + 7) / 8, 256, 16 * 512 * 4>>>(
        hidden, 0, 1, w_hh, b_hh, nullptr, nullptr, nullptr, 3 * HH, 512);
    k_combine<<<(BB * HH + 255) / 256, 256>>>(hidden, out, write_nh, BB * HH);
    k_rowgemm<true><<<(MM1 + 7) / 8, 256, 16 * 512 * 4>>>(
        nullptr, 1, 2, l1w, l1b, pr1, bg1, bb1, MM1, 512);
    k_lin2_out<<<(MM2 / 4 + 7) / 8, 256>>>(l2w, l2b, pr2, bg2, bb2, wo, out, MM2);
}

// round 14
// speedup vs baseline: 1.3440x; 1.0891x over previous
#include <cuda_runtime.h>
#include <math.h>

#define BB   16
#define NN   4096
#define EE   65536
#define HH   512
#define MM1  1024
#define MM2  32768

// ---- device scratch. NEVER named in host code (host shadows + ATS would
// silently write host memory and trip the harness mem guard). ---------------
__device__ int   g_deg[NN];
__device__ int   g_off[NN + 1];
__device__ int   g_cur[NN];
__device__ int   g_src[EE];
__device__ float g_hA [(size_t)BB * NN * 32];
__device__ float g_hB [(size_t)BB * NN * 32];
__device__ float g_w  [(size_t)BB * EE];        // edge softmax weights
__device__ float g_as0[(size_t)BB * NN], g_ad0[(size_t)BB * NN];
__device__ float g_as1[(size_t)BB * NN], g_ad1[(size_t)BB * NN];
__device__ float g_gi [(size_t)BB * 3 * HH];
__device__ float g_gh [(size_t)BB * 3 * HH];
__device__ float g_nh [(size_t)BB * HH];
__device__ float g_o1 [(size_t)BB * MM1];
__device__ float g_o2 [(size_t)BB * MM2];       // lin2 output (plain stores)

__device__ __forceinline__ float lrelu(float v) { return v >= 0.f ? v : 0.2f * v; }

// ---- warp rowgemm: C[b][row] = A[b]·W[row] + bias (A read via L1) ---------
__device__ __forceinline__ void rowgemm_warp(
    const float* __restrict__ A, const float* __restrict__ W,
    const float* __restrict__ bias,
    const float* pr, const float* bg, const float* bb, bool epi,
    float* __restrict__ C, int row, int M, int K, int lane) {
    float acc[16];
#pragma unroll
    for (int b2 = 0; b2 < 16; b2++) acc[b2] = 0.f;
    const float* w = W + (size_t)row * K;
    for (int k = lane * 4; k < K; k += 128) {
        float4 wv = *(const float4*)(w + k);
#pragma unroll
        for (int b2 = 0; b2 < 16; b2++) {
            float4 av = __ldg((const float4*)(A + (size_t)b2 * K + k));
            acc[b2] += wv.x * av.x + wv.y * av.y + wv.z * av.z + wv.w * av.w;
        }
    }
#pragma unroll
    for (int b2 = 0; b2 < 16; b2++) {
#pragma unroll
        for (int o = 16; o > 0; o >>= 1) acc[b2] += __shfl_xor_sync(0xffffffffu, acc[b2], o);
    }
    if (lane == 0) {
        const float inv = rsqrtf(1.f + 1e-5f);
#pragma unroll
        for (int b2 = 0; b2 < 16; b2++) {
            float t = acc[b2] + bias[row];
            if (epi) {
                t = t >= 0.f ? t : pr[row] * t;
                t = t * inv * bg[row] + bb[row];
            }
            C[(size_t)b2 * M + row] = t;
        }
    }
}

// ============ #1: zero_deg + GRU input/hidden GEMMs ========================
// blocks 0..191: gi rows (8/block); 192..383: gh rows; 384..399: zero_deg.
__global__ void k_pre(const float* __restrict__ x, const float* __restrict__ hidden,
                      const float* __restrict__ w_ih, const float* __restrict__ b_ih,
                      const float* __restrict__ w_hh, const float* __restrict__ b_hh) {
    int blk = blockIdx.x;
    int wid = threadIdx.x >> 5, lane = threadIdx.x & 31;
    if (blk < 192) {
        int row = blk * 8 + wid;               // 0..1535
        rowgemm_warp(x, w_ih, b_ih, 0, 0, 0, false, g_gi, row, 3 * HH, 256, lane);
    } else if (blk < 384) {
        int row = (blk - 192) * 8 + wid;       // 0..1535
        rowgemm_warp(hidden, w_hh, b_hh, 0, 0, 0, false, g_gh, row, 3 * HH, HH, lane);
    } else {
        int i = (blk - 384) * 256 + threadIdx.x;
        if (i < NN) g_deg[i] = 0;
    }
}

// ============ #2: hist + GRU combine =======================================
// blocks 0..255: hist; 256..287: combine.
__global__ void k_hist_comb(const int* __restrict__ ei,
                            const float* __restrict__ hidden,
                            float* __restrict__ out, int write_nh) {
    int blk = blockIdx.x;
    if (blk < 256) {
        int i = blk * 256 + threadIdx.x;
        if (i < EE) atomicAdd(&g_deg[ei[EE + i]], 1);
    } else {
        int t = (blk - 256) * 256 + threadIdx.x;
        if (t >= BB * HH) return;
        int b = t / HH, j = t % HH;
        size_t base = (size_t)b * 3 * HH;
        float ir = g_gi[base + j], iz = g_gi[base + HH + j], in_ = g_gi[base + 2 * HH + j];
        float hr = g_gh[base + j], hz = g_gh[base + HH + j], hn = g_gh[base + 2 * HH + j];
        float r = 1.f / (1.f + expf(-(ir + hr)));
        float z = 1.f / (1.f + expf(-(iz + hz)));
        float n = tanhf(in_ + r * hn);
        float hp = hidden[(size_t)b * HH + j];
        float nh = (1.f - z) * n + z * hp;
        g_nh[(size_t)b * HH + j] = nh;
        if (write_nh) out[(size_t)BB * NN * 3 + (size_t)b * HH + j] = nh;
    }
}

// ============ #3: scan + feat3 + lin1 ======================================
// block 0: scan; blocks 1..128: lin1 rows (8/block); 129..: feat3 warps.
__global__ void k_mid(const float* __restrict__ svp,
                      const float* __restrict__ W0,
                      const float* __restrict__ a0s, const float* __restrict__ a0d,
                      const float* __restrict__ l1w, const float* __restrict__ l1b,
                      const float* __restrict__ pr1, const float* __restrict__ bg1,
                      const float* __restrict__ bb1) {
    int blk = blockIdx.x;
    int tid = threadIdx.x;
    int wid = tid >> 5, lane = tid & 31;
    if (blk == 0) {
        __shared__ int s_scan[256];
        int base = tid * 16;
        int v[16]; int sum = 0;
#pragma unroll
        for (int i = 0; i < 16; i++) { v[i] = g_deg[base + i]; sum += v[i]; }
        s_scan[tid] = sum;
        __syncthreads();
        for (int o = 1; o < 256; o <<= 1) {
            int t2 = (tid >= o) ? s_scan[tid - o] : 0;
            __syncthreads();
            s_scan[tid] += t2;
            __syncthreads();
        }
        int run = s_scan[tid] - sum;
#pragma unroll
        for (int i = 0; i < 16; i++) {
            g_off[base + i] = run; g_cur[base + i] = run; run += v[i];
        }
        if (tid == 255) g_off[NN] = run;
    } else if (blk <= 128) {
        int row = (blk - 1) * 8 + wid;         // 0..1023
        rowgemm_warp(g_nh, l1w, l1b, pr1, bg1, bb1, true, g_o1, row, MM1, HH, lane);
    } else {
        int gw = (blk - 129) * 8 + wid;        // 0..65535
        if (gw >= BB * NN) return;
        const float* xv = svp + (size_t)gw * 3;
        float v0 = xv[0], v1 = xv[1], v2 = xv[2];
        float hv = W0[lane * 3] * v0 + W0[lane * 3 + 1] * v1 + W0[lane * 3 + 2] * v2;
        g_hA[(size_t)gw * 32 + lane] = hv;
        float ps = hv * a0s[lane];
        float pd = hv * a0d[lane];
#pragma unroll
        for (int o = 16; o > 0; o >>= 1) {
            ps += __shfl_xor_sync(0xffffffffu, ps, o);
            pd += __shfl_xor_sync(0xffffffffu, pd, o);
        }
        if (lane == 0) { g_as0[gw] = ps; g_ad0[gw] = pd; }
    }
}

// ============ #4: lin2 (-> g_o2, plain stores) + scatter ===================
// blocks 0..1023: lin2 4-row warps; 1024..1279: scatter.  <-- PROFILED SLOT
__global__ void k_lin2_scat(const float* __restrict__ W,
                            const float* __restrict__ bias,
                            const float* __restrict__ pr,
                            const float* __restrict__ bg,
                            const float* __restrict__ bb,
                            const int* __restrict__ ei) {
    int blk = blockIdx.x;
    int wid = threadIdx.x >> 5, lane = threadIdx.x & 31;
    if (blk < 1024) {
        int m0 = (blk * 8 + wid) * 4;          // 0..32764
        float acc[4][16];
#pragma unroll
        for (int r = 0; r < 4; r++)
#pragma unroll
            for (int b2 = 0; b2 < 16; b2++) acc[r][b2] = 0.f;
        const float* wr = W + (size_t)m0 * MM1;
        for (int k = lane * 4; k < MM1; k += 128) {
            float4 wv0 = __ldcs((const float4*)(wr + k));
            float4 wv1 = __ldcs((const float4*)(wr + MM1 + k));
            float4 wv2 = __ldcs((const float4*)(wr + 2 * MM1 + k));
            float4 wv3 = __ldcs((const float4*)(wr + 3 * MM1 + k));
#pragma unroll
            for (int b2 = 0; b2 < 16; b2++) {
                float4 av = *(const float4*)(g_o1 + (size_t)b2 * MM1 + k);
                acc[0][b2] += wv0.x * av.x + wv0.y * av.y + wv0.z * av.z + wv0.w * av.w;
                acc[1][b2] += wv1.x * av.x + wv1.y * av.y + wv1.z * av.z + wv1.w * av.w;
                acc[2][b2] += wv2.x * av.x + wv2.y * av.y + wv2.z * av.z + wv2.w * av.w;
                acc[3][b2] += wv3.x * av.x + wv3.y * av.y + wv3.z * av.z + wv3.w * av.w;
            }
        }
        float mine[4];
#pragma unroll
        for (int r = 0; r < 4; r++) {
            mine[r] = 0.f;
#pragma unroll
            for (int b2 = 0; b2 < 16; b2++) {
                float v = acc[r][b2];
#pragma unroll
                for (int o = 16; o > 0; o >>= 1) v += __shfl_xor_sync(0xffffffffu, v, o);
                if (lane == b2) mine[r] = v;
            }
        }
        if (lane < 16) {
            const float inv = rsqrtf(1.f + 1e-5f);
#pragma unroll
            for (int r = 0; r < 4; r++) {
                int mrow = m0 + r;
                float t = mine[r] + bias[mrow];
                t = t >= 0.f ? t : pr[mrow] * t;
                t = t * inv * bg[mrow] + bb[mrow];
                g_o2[(size_t)lane * MM2 + mrow] = t;
            }
        }
    } else {
        int i = (blk - 1024) * 256 + threadIdx.x;
        if (i < EE) {
            int d = ei[EE + i];
            int pos = atomicAdd(&g_cur[d], 1);
            g_src[pos] = ei[i];
        }
    }
}

// ---- single-pass GAT aggregate, no inner-loop shfls (R13-validated) -------
template <int LAYER>
__device__ __forceinline__ float gat_aggregate(int gw, int lane, int b, int d) {
    const float* asv = (LAYER == 0) ? g_as0 : g_as1;
    const float* adv = (LAYER == 0) ? g_ad0 : g_ad1;
    const float* hsrc = (LAYER == 0) ? g_hA : g_hB;
    const float* asb = asv + (size_t)b * NN;
    const float* hb = hsrc + (size_t)b * NN * 32;
    float add = adv[gw];
    int beg = g_off[d], end = g_off[d + 1];
    float* wb = g_w + (size_t)b * EE;

    float wsum = 0.f;
    for (int i = beg + lane; i < end; i += 32) {
        float w = expf(lrelu(asb[g_src[i]] + add));
        wb[i] = w;
        wsum += w;
    }
#pragma unroll
    for (int o = 16; o > 0; o >>= 1) wsum += __shfl_xor_sync(0xffffffffu, wsum, o);
    float wself = expf(lrelu(asb[d] + add));
    wsum += wself;
    __syncwarp();

    float acc = wself * hb[(size_t)d * 32 + lane];
#pragma unroll 4
    for (int j = beg; j < end; j++) {
        float w = wb[j];
        int   s = g_src[j];
        acc += w * hb[(size_t)s * 32 + lane];
    }
    return acc / wsum;
}

// ============ #5: agg0 fused with layer-1 transform ========================
__global__ void k_agg0_feat1(const float* __restrict__ b0,
                             const float* __restrict__ W1,
                             const float* __restrict__ a1s,
                             const float* __restrict__ a1d,
                             int nwork) {
    int gw = (blockIdx.x * blockDim.x + threadIdx.x) >> 5;
    int lane = threadIdx.x & 31;
    if (gw >= nwork) return;
    int b = gw >> 12;
    int d = gw & (NN - 1);

    float gat = gat_aggregate<0>(gw, lane, b, d) + b0[lane];

    float hv = 0.f;
#pragma unroll
    for (int k = 0; k < 32; k++) {
        float gk = __shfl_sync(0xffffffffu, gat, k);
        hv += W1[lane * 32 + k] * gk;
    }
    g_hB[(size_t)gw * 32 + lane] = hv;
    float ps = hv * a1s[lane];
    float pd = hv * a1d[lane];
#pragma unroll
    for (int o = 16; o > 0; o >>= 1) {
        ps += __shfl_xor_sync(0xffffffffu, ps, o);
        pd += __shfl_xor_sync(0xffffffffu, pd, o);
    }
    if (lane == 0) { g_as1[gw] = ps; g_ad1[gw] = pd; }
}

// ============ #6: agg1 fused with FULL output projection ===================
// lane<8 also folds the MLP slice (g_o2) into the same butterfly reduction.
__global__ void k_agg1_out(const float* __restrict__ b1,
                           const float* __restrict__ wo,   // [3 x 40]
                           const float* __restrict__ bo,   // [3]
                           float* __restrict__ out,
                           int nwork) {
    int gw = (blockIdx.x * blockDim.x + threadIdx.x) >> 5;
    int lane = threadIdx.x & 31;
    if (gw >= nwork) return;
    int b = gw >> 12;
    int d = gw & (NN - 1);

    float gat = gat_aggregate<1>(gw, lane, b, d) + b1[lane];

    float o2v = (lane < 8) ? g_o2[(size_t)b * MM2 + d * 8 + lane] : 0.f;
    float s0 = gat * wo[8 + lane] + ((lane < 8) ? o2v * wo[lane] : 0.f);
    float s1 = gat * wo[48 + lane] + ((lane < 8) ? o2v * wo[40 + lane] : 0.f);
    float s2 = gat * wo[88 + lane] + ((lane < 8) ? o2v * wo[80 + lane] : 0.f);
#pragma unroll
    for (int o = 16; o > 0; o >>= 1) {
        s0 += __shfl_xor_sync(0xffffffffu, s0, o);
        s1 += __shfl_xor_sync(0xffffffffu, s1, o);
        s2 += __shfl_xor_sync(0xffffffffu, s2, o);
    }
    if (lane == 0) {
        size_t base = (size_t)gw * 3;
        out[base + 0] = bo[0] + s0;
        out[base + 1] = bo[1] + s1;
        out[base + 2] = bo[2] + s2;
    }
}

// ---------------- launch ----------------------------------------------------
extern "C" void kernel_launch(void* const* d_in, const int* in_sizes, int n_in,
                              void* d_out, int out_size) {
    const float* x      = (const float*)d_in[0];
    const float* svp    = (const float*)d_in[1];
    const float* hidden = (const float*)d_in[2];
    const int*   ei     = (const int*)  d_in[3];
    const float* W0     = (const float*)d_in[4];
    const float* a0s    = (const float*)d_in[5];
    const float* a0d    = (const float*)d_in[6];
    const float* b0     = (const float*)d_in[7];
    const float* W1     = (const float*)d_in[8];
    const float* a1s    = (const float*)d_in[9];
    const float* a1d    = (const float*)d_in[10];
    const float* b1     = (const float*)d_in[11];
    const float* w_ih   = (const float*)d_in[12];
    const float* w_hh   = (const float*)d_in[13];
    const float* b_ih   = (const float*)d_in[14];
    const float* b_hh   = (const float*)d_in[15];
    const float* l1w    = (const float*)d_in[16];
    const float* l1b    = (const float*)d_in[17];
    const float* pr1    = (const float*)d_in[18];
    const float* bg1    = (const float*)d_in[19];
    const float* bb1    = (const float*)d_in[20];
    const float* l2w    = (const float*)d_in[21];
    const float* l2b    = (const float*)d_in[22];
    const float* pr2    = (const float*)d_in[23];
    const float* bg2    = (const float*)d_in[24];
    const float* bb2    = (const float*)d_in[25];
    const float* wo     = (const float*)d_in[26];
    const float* bo     = (const float*)d_in[27];
    float* out = (float*)d_out;

    int write_nh = (out_size >= BB * NN * 3 + BB * HH) ? 1 : 0;

    // #1 zero_deg + gi + gh
    k_pre<<<400, 256>>>(x, hidden, w_ih, b_ih, w_hh, b_hh);
    // #2 hist + combine
    k_hist_comb<<<288, 256>>>(ei, hidden, out, write_nh);
    // #3 scan + lin1 + feat3
    k_mid<<<1 + 128 + 8192, 256>>>(svp, W0, a0s, a0d, l1w, l1b, pr1, bg1, bb1);
    // #4 lin2 -> g_o2 + scatter      <-- profiled slot
    k_lin2_scat<<<1024 + 256, 256>>>(l2w, l2b, pr2, bg2, bb2, ei);
    // #5 agg0 + layer-1 transform
    k_agg0_feat1<<<(BB * NN) / 8, 256>>>(b0, W1, a1s, a1d, BB * NN);
    // #6 agg1 + full output projection
    k_agg1_out<<<(BB * NN) / 8, 256>>>(b1, wo, bo, out, BB * NN);
}